// round 1
// baseline (speedup 1.0000x reference)
#include <cuda_runtime.h>

#define DT 0.016f
#define MASS_INV (1.0f/2.8f)
#define TWO_PI 6.28318530717958647693f
#define INV_TWO_PI 0.15915494309189533577f

// Compile-time M = FORCE_MATRIX @ FORCE_MATRIX.T (sparse by wheel symmetry):
// angles 60,130,230,300 deg; M01 = M02 = 0.
#define M00 2.6736481776669305f
#define M11 1.3263518223330695f
#define M12 (-0.025701769682033216f)
#define M22 0.0324f

__device__ __forceinline__ float softplus_f(float x) {
    // matches jax.nn.softplus within fp32 rounding for the parameter range here
    return log1pf(expf(x));
}

__global__ __launch_bounds__(32)
void OmniRobotPhysics_kernel(
    const float* __restrict__ init,
    const float* __restrict__ cmd,
    const float* __restrict__ com,
    const float* __restrict__ inertia_p,
    const float* __restrict__ gain_p,
    const float* __restrict__ grip_p,
    const float* __restrict__ dragv_p,
    const float* __restrict__ dragc_p,
    float* __restrict__ out,
    int B, int T)
{
    int b = blockIdx.x * blockDim.x + threadIdx.x;
    if (b >= B) return;

    // ---- scalar parameter prep (once per thread; trivial cost) ----
    const float inertia = softplus_f(inertia_p[0]) + 1e-4f;
    const float gain    = softplus_f(gain_p[0]);
    const float grip    = softplus_f(grip_p[0]);
    const float dv0 = softplus_f(dragv_p[0]);
    const float dv1 = softplus_f(dragv_p[1]);
    const float dv2 = softplus_f(dragv_p[2]);
    const float dc0 = softplus_f(dragc_p[0]);
    const float dc1 = softplus_f(dragc_p[1]);
    const float dc2 = softplus_f(dragc_p[2]);
    const float dx = com[0], dy = com[1];
    const float invI = 1.0f / inertia;

    // A = gain*M + grip*I  (grip term comes from -grip*(bv - cmd))
    const float A00 = fmaf(gain, M00, grip);
    const float A11 = fmaf(gain, M11, grip);
    const float A12 = gain * M12;
    const float A22 = fmaf(gain, M22, grip);

    // ---- state load ----
    const float* ip = init + (size_t)b * 6;
    float x  = ip[0], y  = ip[1], th = ip[2];
    float vx = ip[3], vy = ip[4], om = ip[5];

    const float* crow = cmd + (size_t)b * T * 3;
    float*       orow = out + (size_t)b * (T + 1) * 6;

    // write t = 0 (initial state)
    {
        float2* p = (float2*)orow;
        p[0] = make_float2(x, y);
        p[1] = make_float2(th, vx);
        p[2] = make_float2(vy, om);
    }

    auto step = [&](float cx, float cy, float cz, int to) {
        float s, c;
        __sincosf(th, &s, &c);
        // world -> body velocity
        float vxb = fmaf(vx, c, vy * s);
        float vyb = fmaf(vy, c, -vx * s);
        // tracking error
        float ex = cx - vxb;
        float ey = cy - vyb;
        float eo = cz - om;
        // coulomb drag sign terms
        float sgx = (vxb > 0.f) ? dc0 : ((vxb < 0.f) ? -dc0 : 0.f);
        float sgy = (vyb > 0.f) ? dc1 : ((vyb < 0.f) ? -dc1 : 0.f);
        float sgo = (om  > 0.f) ? dc2 : ((om  < 0.f) ? -dc2 : 0.f);
        // generalized forces (sparse A)
        float Fx  = fmaf(A00, ex, fmaf(-dv0, vxb, -sgx));
        float Fy  = fmaf(A11, ey, fmaf(A12, eo, fmaf(-dv1, vyb, -sgy)));
        float Tau = fmaf(A12, ey, fmaf(A22, eo, fmaf(-dv2, om,  -sgo)));
        // torque about COM
        float TauC = Tau - (dx * Fy - dy * Fx);
        float accx = Fx * MASS_INV;
        float accy = Fy * MASS_INV;
        float aal  = TauC * invI;
        float om2  = om * om;
        float axb = accx - aal * dy - om2 * dx;
        float ayb = accy + aal * dx - om2 * dy;
        // body -> world acceleration
        float axw = fmaf(axb, c, -ayb * s);
        float ayw = fmaf(axb, s,  ayb * c);
        // integrate (semi-implicit per reference ordering)
        vx = fmaf(axw, DT, vx);
        vy = fmaf(ayw, DT, vy);
        om = fmaf(aal, DT, om);
        x  = fmaf(vx, DT, x);
        y  = fmaf(vy, DT, y);
        th = fmaf(om, DT, th);
        // wrap to [-pi, pi]  (== atan2(sin, cos) up to fp rounding)
        th = fmaf(-TWO_PI, rintf(th * INV_TWO_PI), th);
        // store state
        float2* p = (float2*)(orow + (size_t)to * 6);
        p[0] = make_float2(x, y);
        p[1] = make_float2(th, vx);
        p[2] = make_float2(vy, om);
    };

    if ((T & 3) == 0) {
        // vectorized path: 3x float4 loads cover 4 steps of commands.
        const float4* c4 = (const float4*)crow;
        float4 ca = c4[0], cb = c4[1], cc = c4[2];
        for (int t = 0; t < T; t += 4) {
            float4 na = make_float4(0.f,0.f,0.f,0.f);
            float4 nb = na, nc = na;
            if (t + 4 < T) {
                int i = ((t >> 2) + 1) * 3;
                na = c4[i]; nb = c4[i + 1]; nc = c4[i + 2];
            }
            step(ca.x, ca.y, ca.z, t + 1);
            step(ca.w, cb.x, cb.y, t + 2);
            step(cb.z, cb.w, cc.x, t + 3);
            step(cc.y, cc.z, cc.w, t + 4);
            ca = na; cb = nb; cc = nc;
        }
    } else {
        for (int t = 0; t < T; t++) {
            const float* cp = crow + (size_t)t * 3;
            step(cp[0], cp[1], cp[2], t + 1);
        }
    }
}

extern "C" void kernel_launch(void* const* d_in, const int* in_sizes, int n_in,
                              void* d_out, int out_size)
{
    (void)n_in; (void)out_size;
    const float* init = (const float*)d_in[0];
    const float* cmd  = (const float*)d_in[1];
    const float* com  = (const float*)d_in[2];
    const float* ine  = (const float*)d_in[3];
    const float* gai  = (const float*)d_in[4];
    const float* gri  = (const float*)d_in[5];
    const float* dvp  = (const float*)d_in[6];
    const float* dcp  = (const float*)d_in[7];

    int B = in_sizes[0] / 6;
    int T = in_sizes[1] / (B * 3);

    int threads = 32;                      // 1 warp/CTA: spread 256 CTAs over 152 SMs
    int blocks = (B + threads - 1) / threads;
    OmniRobotPhysics_kernel<<<blocks, threads>>>(
        init, cmd, com, ine, gai, gri, dvp, dcp, (float*)d_out, B, T);
}